// round 3
// baseline (speedup 1.0000x reference)
#include <cuda_runtime.h>

#define TB 2048
#define TT 336
#define TF 10

// ---------------- device scratch (static; no allocations allowed) ----------------
__device__ float dW1g[2 * 80 * 4 * 72];      // [dir][k][gate][unit(pad 72)]
__device__ float dB1g[2 * 4 * 72];
__device__ float dW2g[2 * 161 * 4 * 24];     // [dir][k][gate][unit(pad 24)]
__device__ float dB2g[2 * 4 * 24];
__device__ float dH1[2048 * 336 * 140];      // layer1 output, [b][t][140]
__device__ float dH2[2048 * 336 * 42];       // layer2 output, [b][t][42]

// ---------------- f32x2 packed-FMA helpers (Blackwell-only SASS path) ----------------
__device__ __forceinline__ unsigned long long pk2(float v) {
    unsigned long long r;
    asm("mov.b64 %0, {%1, %2};" : "=l"(r) : "f"(v), "f"(v));
    return r;
}
__device__ __forceinline__ float2 up2(unsigned long long v) {
    float2 r;
    asm("mov.b64 {%0, %1}, %2;" : "=f"(r.x), "=f"(r.y) : "l"(v));
    return r;
}
__device__ __forceinline__ void fma2(unsigned long long& d, unsigned long long a, unsigned long long b) {
    asm("fma.rn.f32x2 %0, %1, %2, %3;" : "=l"(d) : "l"(a), "l"(b), "l"(d));
}

__device__ __forceinline__ float sigf(float x) {
    return __fdividef(1.f, 1.f + __expf(-x));
}
__device__ __forceinline__ float tanhf_(float x) {
    return 2.f * __fdividef(1.f, 1.f + __expf(-2.f * x)) - 1.f;
}

// ---------------- weight prep ----------------
__global__ void prep1(const float* wfih, const float* wfhh, const float* bfih, const float* bfhh,
                      const float* wbih, const float* wbhh, const float* bbih, const float* bbhh) {
    int idx = blockIdx.x * blockDim.x + threadIdx.x;
    if (idx < 2 * 80 * 288) {
        int d = idx / (80 * 288);
        int rem = idx % (80 * 288);
        int k = rem / 288;
        int j = rem % 288;
        int g = j / 72, u = j % 72;
        const float* wih = d ? wbih : wfih;
        const float* whh = d ? wbhh : wfhh;
        float v = 0.f;
        if (u < 70) {
            int row = g * 70 + u;
            v = (k < 10) ? wih[row * 10 + k] : whh[row * 70 + (k - 10)];
        }
        dW1g[idx] = v;
    }
    if (idx < 2 * 288) {
        int d = idx / 288;
        int j = idx % 288;
        int g = j / 72, u = j % 72;
        const float* bih = d ? bbih : bfih;
        const float* bhh = d ? bbhh : bfhh;
        dB1g[idx] = (u < 70) ? bih[g * 70 + u] + bhh[g * 70 + u] : 0.f;
    }
}

__global__ void prep2(const float* wfih, const float* wfhh, const float* bfih, const float* bfhh,
                      const float* wbih, const float* wbhh, const float* bbih, const float* bbhh) {
    int idx = blockIdx.x * blockDim.x + threadIdx.x;
    if (idx < 2 * 161 * 96) {
        int d = idx / (161 * 96);
        int rem = idx % (161 * 96);
        int k = rem / 96;
        int j = rem % 96;
        int g = j / 24, u = j % 24;
        const float* wih = d ? wbih : wfih;
        const float* whh = d ? wbhh : wfhh;
        float v = 0.f;
        if (u < 21) {
            int row = g * 21 + u;
            v = (k < 140) ? wih[row * 140 + k] : whh[row * 21 + (k - 140)];
        }
        dW2g[idx] = v;
    }
    if (idx < 2 * 96) {
        int d = idx / 96;
        int j = idx % 96;
        int g = j / 24, u = j % 24;
        const float* bih = d ? bbih : bfih;
        const float* bhh = d ? bbhh : bfhh;
        dB2g[idx] = (u < 21) ? bih[g * 21 + u] + bhh[g * 21 + u] : 0.f;
    }
}

// ---------------- layer 1: bidirectional LSTM, F=10 -> H=70 ----------------
// grid (64, 2): 32 batch rows per CTA, blockIdx.y = direction. 280 threads:
// thread = (rowgroup rg in 0..7 [4 rows], unit-pair up in 0..34 [2 hidden units]).
// Gates i,f,g,o for the same units live in one thread -> local activations, c in regs.
#define S1 36   // sIn row stride (not mult of 32: kills h-writeback bank conflicts)
__global__ __launch_bounds__(280) void lstm1(const float* __restrict__ x) {
    extern __shared__ float sm[];
    float* sW = sm;                     // 80*288
    float* sB = sW + 80 * 288;          // 288
    float* sIn = sB + 288;              // 80*S1, [k][row]
    int dir = blockIdx.y;
    int b0 = blockIdx.x * 32;
    int tid = threadIdx.x;

    const float* gW = dW1g + dir * 80 * 288;
    for (int i = tid; i < 80 * 288; i += 280) sW[i] = gW[i];
    for (int i = tid; i < 288; i += 280) sB[i] = dB1g[dir * 288 + i];
    for (int i = tid; i < 80 * S1; i += 280) sIn[i] = 0.f;

    int up = tid % 35, rg = tid / 35;
    int r0 = rg * 4, u0 = up * 2;
    float c[4][2];
#pragma unroll
    for (int r = 0; r < 4; r++) { c[r][0] = 0.f; c[r][1] = 0.f; }
    __syncthreads();

    float2 bi = *(float2*)&sB[0 * 72 + u0];
    float2 bf = *(float2*)&sB[1 * 72 + u0];
    float2 bg = *(float2*)&sB[2 * 72 + u0];
    float2 bo = *(float2*)&sB[3 * 72 + u0];

    const float* pin = sIn + r0;
    const float* pw = sW + u0;

    for (int s = 0; s < TT; s++) {
        int t = dir ? (TT - 1 - s) : s;
        // stage x into sIn[0..9][*]
        for (int i = tid; i < 320; i += 280) {
            int r = i / 10, f = i % 10;
            sIn[f * S1 + r] = x[((b0 + r) * TT + t) * 10 + f];
        }
        __syncthreads();

        unsigned long long acc[4][4];
#pragma unroll
        for (int r = 0; r < 4; r++)
#pragma unroll
            for (int g = 0; g < 4; g++) acc[r][g] = 0ull;

#pragma unroll 4
        for (int k = 0; k < 80; k++) {
            float2 v01 = *(const float2*)(pin + k * S1);
            float2 v23 = *(const float2*)(pin + k * S1 + 2);
            unsigned long long a0 = pk2(v01.x), a1 = pk2(v01.y);
            unsigned long long a2 = pk2(v23.x), a3 = pk2(v23.y);
#pragma unroll
            for (int g = 0; g < 4; g++) {
                unsigned long long w = *(const unsigned long long*)(pw + k * 288 + g * 72);
                fma2(acc[0][g], a0, w);
                fma2(acc[1][g], a1, w);
                fma2(acc[2][g], a2, w);
                fma2(acc[3][g], a3, w);
            }
        }

        float hv[4][2];
#pragma unroll
        for (int r = 0; r < 4; r++) {
            float2 gi = up2(acc[r][0]); gi.x += bi.x; gi.y += bi.y;
            float2 gf = up2(acc[r][1]); gf.x += bf.x; gf.y += bf.y;
            float2 gg = up2(acc[r][2]); gg.x += bg.x; gg.y += bg.y;
            float2 go = up2(acc[r][3]); go.x += bo.x; go.y += bo.y;
            float c0 = sigf(gf.x) * c[r][0] + sigf(gi.x) * tanhf_(gg.x);
            float c1 = sigf(gf.y) * c[r][1] + sigf(gi.y) * tanhf_(gg.y);
            c[r][0] = c0; c[r][1] = c1;
            hv[r][0] = sigf(go.x) * tanhf_(c0);
            hv[r][1] = sigf(go.y) * tanhf_(c1);
        }
        __syncthreads();
#pragma unroll
        for (int r = 0; r < 4; r++) {
            sIn[(10 + u0) * S1 + r0 + r] = hv[r][0];
            sIn[(11 + u0) * S1 + r0 + r] = hv[r][1];
            float2 st = make_float2(hv[r][0], hv[r][1]);
            *(float2*)&dH1[((b0 + r0 + r) * TT + t) * 140 + dir * 70 + u0] = st;
        }
    }
}

// ---------------- layer 2: bidirectional LSTM, 140 -> H=21 (padded to 22) ----------------
// grid (64, 2), 176 threads: (rowgroup rg in 0..15 [2 rows], unit-pair up in 0..10).
__global__ __launch_bounds__(176) void lstm2() {
    extern __shared__ float sm[];
    float* sW = sm;                     // 161*96
    float* sB = sW + 161 * 96;          // 96
    float* sIn = sB + 96;               // 161*S1
    int dir = blockIdx.y;
    int b0 = blockIdx.x * 32;
    int tid = threadIdx.x;

    const float* gW = dW2g + dir * 161 * 96;
    for (int i = tid; i < 161 * 96; i += 176) sW[i] = gW[i];
    for (int i = tid; i < 96; i += 176) sB[i] = dB2g[dir * 96 + i];
    for (int i = tid; i < 161 * S1; i += 176) sIn[i] = 0.f;

    int up = tid % 11, rg = tid / 11;
    int r0 = rg * 2, u0 = up * 2;
    float c[2][2];
    c[0][0] = c[0][1] = c[1][0] = c[1][1] = 0.f;
    __syncthreads();

    float2 bi = *(float2*)&sB[0 + u0];
    float2 bf = *(float2*)&sB[24 + u0];
    float2 bg = *(float2*)&sB[48 + u0];
    float2 bo = *(float2*)&sB[72 + u0];

    const float* pin = sIn + r0;
    const float* pw = sW + u0;

    for (int s = 0; s < TT; s++) {
        int t = dir ? (TT - 1 - s) : s;
        // stage h1[b][t][0..139] -> sIn[k][r] (coalesced LDG, k fastest)
        for (int i = tid; i < 140 * 32; i += 176) {
            int r = i / 140, k = i % 140;
            sIn[k * S1 + r] = dH1[((b0 + r) * TT + t) * 140 + k];
        }
        __syncthreads();

        unsigned long long acc[2][4];
#pragma unroll
        for (int r = 0; r < 2; r++)
#pragma unroll
            for (int g = 0; g < 4; g++) acc[r][g] = 0ull;

#pragma unroll 7
        for (int k = 0; k < 161; k++) {
            float2 v = *(const float2*)(pin + k * S1);
            unsigned long long a0 = pk2(v.x), a1 = pk2(v.y);
#pragma unroll
            for (int g = 0; g < 4; g++) {
                unsigned long long w = *(const unsigned long long*)(pw + k * 96 + g * 24);
                fma2(acc[0][g], a0, w);
                fma2(acc[1][g], a1, w);
            }
        }

        float hv[2][2];
#pragma unroll
        for (int r = 0; r < 2; r++) {
            float2 gi = up2(acc[r][0]); gi.x += bi.x; gi.y += bi.y;
            float2 gf = up2(acc[r][1]); gf.x += bf.x; gf.y += bf.y;
            float2 gg = up2(acc[r][2]); gg.x += bg.x; gg.y += bg.y;
            float2 go = up2(acc[r][3]); go.x += bo.x; go.y += bo.y;
            float c0 = sigf(gf.x) * c[r][0] + sigf(gi.x) * tanhf_(gg.x);
            float c1 = sigf(gf.y) * c[r][1] + sigf(gi.y) * tanhf_(gg.y);
            c[r][0] = c0; c[r][1] = c1;
            hv[r][0] = sigf(go.x) * tanhf_(c0);
            hv[r][1] = sigf(go.y) * tanhf_(c1);
        }
        __syncthreads();
#pragma unroll
        for (int r = 0; r < 2; r++) {
            int b = b0 + r0 + r;
            sIn[(140 + u0) * S1 + r0 + r] = hv[r][0];
            dH2[((size_t)b * TT + t) * 42 + dir * 21 + u0] = hv[r][0];
            if (u0 + 1 < 21) {
                sIn[(141 + u0) * S1 + r0 + r] = hv[r][1];
                dH2[((size_t)b * TT + t) * 42 + dir * 21 + u0 + 1] = hv[r][1];
            }
        }
    }
}

// ---------------- dense head: 42 -> relu 30 -> relu 20 -> 1 ----------------
__global__ __launch_bounds__(256) void dense_head(const float* __restrict__ wd1, const float* __restrict__ bd1,
                                                  const float* __restrict__ wd2, const float* __restrict__ bd2,
                                                  const float* __restrict__ wo, const float* __restrict__ bo,
                                                  float* __restrict__ out) {
    __shared__ float sW1[30 * 42], sb1[30], sW2[20 * 30], sb2[20], swo[20], sbo[1];
    int tid = threadIdx.x;
    for (int i = tid; i < 1260; i += 256) sW1[i] = wd1[i];
    for (int i = tid; i < 600; i += 256) sW2[i] = wd2[i];
    if (tid < 30) sb1[tid] = bd1[tid];
    if (tid < 20) { sb2[tid] = bd2[tid]; swo[tid] = wo[tid]; }
    if (tid == 0) sbo[0] = bo[0];
    __syncthreads();

    int pos = blockIdx.x * 256 + tid;   // grid sized exactly B*T/256
    float in[42];
    const float* p = dH2 + (size_t)pos * 42;
#pragma unroll
    for (int k = 0; k < 42; k++) in[k] = p[k];

    float a[30];
#pragma unroll
    for (int j = 0; j < 30; j++) {
        float s = sb1[j];
#pragma unroll
        for (int k = 0; k < 42; k++) s += in[k] * sW1[j * 42 + k];
        a[j] = fmaxf(s, 0.f);
    }
    float o = sbo[0];
#pragma unroll
    for (int j = 0; j < 20; j++) {
        float s = sb2[j];
#pragma unroll
        for (int k = 0; k < 30; k++) s += a[k] * sW2[j * 30 + k];
        o += fmaxf(s, 0.f) * swo[j];
    }
    out[pos] = o;
}

// ---------------- launch ----------------
extern "C" void kernel_launch(void* const* d_in, const int* in_sizes, int n_in,
                              void* d_out, int out_size) {
    const float* x = (const float*)d_in[0];

    cudaFuncSetAttribute(lstm1, cudaFuncAttributeMaxDynamicSharedMemorySize, (80 * 288 + 288 + 80 * S1) * 4);
    cudaFuncSetAttribute(lstm2, cudaFuncAttributeMaxDynamicSharedMemorySize, (161 * 96 + 96 + 161 * S1) * 4);

    prep1<<<180, 256>>>((const float*)d_in[1], (const float*)d_in[2], (const float*)d_in[3], (const float*)d_in[4],
                        (const float*)d_in[5], (const float*)d_in[6], (const float*)d_in[7], (const float*)d_in[8]);
    prep2<<<121, 256>>>((const float*)d_in[9], (const float*)d_in[10], (const float*)d_in[11], (const float*)d_in[12],
                        (const float*)d_in[13], (const float*)d_in[14], (const float*)d_in[15], (const float*)d_in[16]);

    lstm1<<<dim3(64, 2), 280, (80 * 288 + 288 + 80 * S1) * 4>>>(x);
    lstm2<<<dim3(64, 2), 176, (161 * 96 + 96 + 161 * S1) * 4>>>();

    dense_head<<<(2048 * 336) / 256, 256>>>((const float*)d_in[17], (const float*)d_in[18],
                                            (const float*)d_in[19], (const float*)d_in[20],
                                            (const float*)d_in[21], (const float*)d_in[22],
                                            (float*)d_out);
}